// round 17
// baseline (speedup 1.0000x reference)
#include <cuda_runtime.h>
#include <cuda_bf16.h>
#include <stdint.h>
#include <math.h>

#define MAXN 100000
#define MAXE 3200000

// ---------------- scratch (static device globals) ---------------------------
__device__ int          g_cursor[MAXN];
__device__ int          g_rowptr[MAXN + 1];
__device__ int          g_col[MAXE];
__device__ int          g_bsum[256];
__device__ int          g_ticket[8];
__device__ float        g_z[4][MAXN * 64];
__device__ unsigned int g_zh[3][MAXN * 32];
__device__ float        g_u[MAXN * 64];
__device__ float        g_statsA[4][128];

__device__ __forceinline__ float lrelu(float x) { return x >= 0.f ? x : 0.01f * x; }

__device__ __forceinline__ unsigned int pack_bf16x2(float2 v) {
    __nv_bfloat162 b = __float22bfloat162_rn(v);
    return *(unsigned int*)&b;
}
__device__ __forceinline__ float bf_lo(unsigned int w) { return __int_as_float((int)(w << 16)); }
__device__ __forceinline__ float bf_hi(unsigned int w) { return __int_as_float((int)(w & 0xffff0000u)); }

// ---------------- init -------------------------------------------------------
__global__ void k_zero(int n) {
    int i = blockIdx.x * blockDim.x + threadIdx.x;
    if (i < n) g_cursor[i] = 0;
    if (i < 512) ((float*)g_statsA)[i] = 0.f;
    if (i < 8) g_ticket[i] = 0;
}

// ---------------- fused hist + embed, 8 atomics in flight ---------------------
__global__ void k_hist4e(const int* __restrict__ dst, int e4, int e,
                         const int* __restrict__ deg, const float* __restrict__ emb, int n) {
    int stride = gridDim.x * blockDim.x;
    int t0 = blockIdx.x * blockDim.x + threadIdx.x;
    const int4* d4 = (const int4*)dst;
    int half = e4 >> 1;
    for (int i = t0; i < half; i += stride) {
        int4 a = d4[i];
        int4 b = d4[i + half];
        atomicAdd(&g_cursor[a.x], 1);
        atomicAdd(&g_cursor[a.y], 1);
        atomicAdd(&g_cursor[a.z], 1);
        atomicAdd(&g_cursor[a.w], 1);
        atomicAdd(&g_cursor[b.x], 1);
        atomicAdd(&g_cursor[b.y], 1);
        atomicAdd(&g_cursor[b.z], 1);
        atomicAdd(&g_cursor[b.w], 1);
    }
    for (int i = 2 * half + t0; i < e4; i += stride) {   // odd e4 leftover
        int4 d = d4[i];
        atomicAdd(&g_cursor[d.x], 1);
        atomicAdd(&g_cursor[d.y], 1);
        atomicAdd(&g_cursor[d.z], 1);
        atomicAdd(&g_cursor[d.w], 1);
    }
    for (int i = e4 * 4 + t0; i < e; i += stride)
        atomicAdd(&g_cursor[dst[i]], 1);
    int total = n * 32;
    for (int i = t0; i < total; i += stride) {
        int node = i >> 5, j = i & 31;
        float2 v = ((const float2*)emb)[deg[node] * 32 + j];
        ((float2*)g_z[0])[i] = v;
        g_zh[0][i] = pack_bf16x2(v);
    }
}

__global__ void k_hist(const int* __restrict__ dst, int e) {
    int stride = gridDim.x * blockDim.x;
    for (int i = blockIdx.x * blockDim.x + threadIdx.x; i < e; i += stride)
        atomicAdd(&g_cursor[dst[i]], 1);
}
__global__ void k_embed(const int* __restrict__ deg, const float* __restrict__ emb, int n) {
    int i = blockIdx.x * blockDim.x + threadIdx.x;
    if (i >= n * 32) return;
    int node = i >> 5, j = i & 31;
    float2 v = ((const float2*)emb)[deg[node] * 32 + j];
    ((float2*)g_z[0])[i] = v;
    g_zh[0][i] = pack_bf16x2(v);
}
__global__ void k_fill(const int* __restrict__ src, const int* __restrict__ dst, int e) {
    int stride = gridDim.x * blockDim.x;
    for (int i = blockIdx.x * blockDim.x + threadIdx.x; i < e; i += stride) {
        int p = atomicAdd(&g_cursor[dst[i]], 1);
        g_col[p] = src[i];
    }
}

__global__ void k_scan1(int n) {
    __shared__ int wsum[32];
    int tid = threadIdx.x, lane = tid & 31, w = tid >> 5;
    int i = blockIdx.x * 1024 + tid;
    int v = (i < n) ? g_cursor[i] : 0;
    int x = v;
    #pragma unroll
    for (int off = 1; off < 32; off <<= 1) {
        int t = __shfl_up_sync(0xffffffffu, x, off);
        if (lane >= off) x += t;
    }
    if (lane == 31) wsum[w] = x;
    __syncthreads();
    if (w == 0) {
        int s = wsum[lane];
        #pragma unroll
        for (int off = 1; off < 32; off <<= 1) {
            int t = __shfl_up_sync(0xffffffffu, s, off);
            if (lane >= off) s += t;
        }
        wsum[lane] = s;
    }
    __syncthreads();
    int incl = x + (w > 0 ? wsum[w - 1] : 0);
    if (i < n) g_rowptr[i] = incl - v;
    if (tid == 1023) g_bsum[blockIdx.x] = incl;
}

__global__ void k_scan2(int nb) {
    __shared__ int ws[4];
    int tid = threadIdx.x, lane = tid & 31, w = tid >> 5;
    int v = (tid < nb) ? g_bsum[tid] : 0;
    int x = v;
    #pragma unroll
    for (int off = 1; off < 32; off <<= 1) {
        int t = __shfl_up_sync(0xffffffffu, x, off);
        if (lane >= off) x += t;
    }
    if (lane == 31) ws[w] = x;
    __syncthreads();
    if (tid == 0) {
        int c = 0;
        #pragma unroll
        for (int k = 0; k < 4; k++) { int t = ws[k]; ws[k] = c; c += t; }
    }
    __syncthreads();
    if (tid < nb) g_bsum[tid] = x - v + ws[w];
}

__global__ void k_scan3(int n, int e) {
    int i = blockIdx.x * 1024 + threadIdx.x;
    if (i < n) {
        int v = g_rowptr[i] + g_bsum[blockIdx.x];
        g_rowptr[i] = v;
        g_cursor[i] = v;
    }
    if (i == 0) g_rowptr[n] = e;
}

// ---------------- fill, 8 atomics in flight ------------------------------------
__global__ void k_fill4(const int* __restrict__ src, const int* __restrict__ dst, int e4, int e) {
    int stride = gridDim.x * blockDim.x;
    int t0 = blockIdx.x * blockDim.x + threadIdx.x;
    const int4* s4 = (const int4*)src;
    const int4* d4 = (const int4*)dst;
    int half = e4 >> 1;
    for (int i = t0; i < half; i += stride) {
        int4 da = d4[i];
        int4 db = d4[i + half];
        int4 sa = s4[i];
        int4 sb = s4[i + half];
        int p0 = atomicAdd(&g_cursor[da.x], 1);
        int p1 = atomicAdd(&g_cursor[da.y], 1);
        int p2 = atomicAdd(&g_cursor[da.z], 1);
        int p3 = atomicAdd(&g_cursor[da.w], 1);
        int q0 = atomicAdd(&g_cursor[db.x], 1);
        int q1 = atomicAdd(&g_cursor[db.y], 1);
        int q2 = atomicAdd(&g_cursor[db.z], 1);
        int q3 = atomicAdd(&g_cursor[db.w], 1);
        g_col[p0] = sa.x; g_col[p1] = sa.y; g_col[p2] = sa.z; g_col[p3] = sa.w;
        g_col[q0] = sb.x; g_col[q1] = sb.y; g_col[q2] = sb.z; g_col[q3] = sb.w;
    }
    for (int i = 2 * half + t0; i < e4; i += stride) {
        int4 d = d4[i];
        int4 s = s4[i];
        int p0 = atomicAdd(&g_cursor[d.x], 1);
        int p1 = atomicAdd(&g_cursor[d.y], 1);
        int p2 = atomicAdd(&g_cursor[d.z], 1);
        int p3 = atomicAdd(&g_cursor[d.w], 1);
        g_col[p0] = s.x; g_col[p1] = s.y; g_col[p2] = s.z; g_col[p3] = s.w;
    }
    for (int i = e4 * 4 + t0; i < e; i += stride) {
        int p = atomicAdd(&g_cursor[dst[i]], 1);
        g_col[p] = src[i];
    }
}

// ---------------- fused GIN layer (frozen R14 form) ---------------------------
__global__ void __launch_bounds__(256) k_layer(
    const float* __restrict__ W1, const float* __restrict__ b1,
    const float* __restrict__ W2, const float* __restrict__ b2,
    const float* __restrict__ epsArr, int l, int n)
{
    __shared__ float4 sW1q[32][32];
    __shared__ float4 sW2q[32][32];
    __shared__ float2 sb1[32];
    __shared__ float2 sb2[32];
    __shared__ float4 sm4[8][2][16];
    __shared__ float4 sh4[8][2][16];
    __shared__ int    sidx[8][2][32];
    __shared__ float  bstat[128];

    int tid = threadIdx.x;
    {
        const float2* w1v = (const float2*)(W1 + l * 4096);
        const float2* w2v = (const float2*)(W2 + l * 4096);
        for (int i = tid; i < 1024; i += 256) {
            int k2 = i >> 5, c = i & 31;
            float2 a = w1v[(2 * k2) * 32 + c];
            float2 b = w1v[(2 * k2 + 1) * 32 + c];
            sW1q[k2][c] = make_float4(a.x, a.y, b.x, b.y);
            float2 a2 = w2v[(2 * k2) * 32 + c];
            float2 b2v = w2v[(2 * k2 + 1) * 32 + c];
            sW2q[k2][c] = make_float4(a2.x, a2.y, b2v.x, b2v.y);
        }
        if (tid < 32) {
            sb1[tid] = ((const float2*)(b1 + l * 64))[tid];
            sb2[tid] = ((const float2*)(b2 + l * 64))[tid];
        }
        if (tid < 128) bstat[tid] = 0.f;
    }
    __syncthreads();

    float ep = 1.0f + epsArr[l];
    const float2*       __restrict__ x2 = (const float2*)g_z[l];
    const unsigned int* __restrict__ xh = g_zh[l];
    float2* o2 = (float2*)g_z[l + 1];
    int w = tid >> 5, lane = tid & 31;
    float ssx = 0.f, ssy = 0.f, sqx = 0.f, sqy = 0.f;
    int pairs = (n + 1) / 2;

    while (true) {
        int tk;
        if (lane == 0) tk = atomicAdd(&g_ticket[l], 1);
        tk = __shfl_sync(0xffffffffu, tk, 0);
        if (tk >= pairs) break;
        int base = tk * 2;
        int nA = base, nB = base + 1;
        bool hasB = (nB < n);

        int bA = g_rowptr[nA], reA = g_rowptr[nA + 1];
        int bB = hasB ? g_rowptr[nB] : 0, reB = hasB ? g_rowptr[nB + 1] : 0;
        float2 xvA = x2[nA * 32 + lane];
        float2 xvB = hasB ? x2[nB * 32 + lane] : make_float2(0.f, 0.f);
        float aA0x = ep * xvA.x, aA0y = ep * xvA.y, aA1x = 0.f, aA1y = 0.f;
        float aB0x = ep * xvB.x, aB0y = ep * xvB.y, aB1x = 0.f, aB1y = 0.f;

        const int4* iA4 = (const int4*)sidx[w][0];
        const int4* iB4 = (const int4*)sidx[w][1];

        while (bA + 32 <= reA && bB + 32 <= reB) {
            sidx[w][0][lane] = g_col[bA + lane];
            sidx[w][1][lane] = g_col[bB + lane];
            __syncwarp();
            #pragma unroll
            for (int q = 0; q < 8; q++) {
                int4 ja = iA4[q];
                int4 jb = iB4[q];
                unsigned int wA0 = xh[ja.x * 32 + lane];
                unsigned int wA1 = xh[ja.y * 32 + lane];
                unsigned int wB0 = xh[jb.x * 32 + lane];
                unsigned int wB1 = xh[jb.y * 32 + lane];
                unsigned int wA2 = xh[ja.z * 32 + lane];
                unsigned int wA3 = xh[ja.w * 32 + lane];
                unsigned int wB2 = xh[jb.z * 32 + lane];
                unsigned int wB3 = xh[jb.w * 32 + lane];
                aA0x += bf_lo(wA0); aA0y += bf_hi(wA0);
                aA1x += bf_lo(wA1); aA1y += bf_hi(wA1);
                aB0x += bf_lo(wB0); aB0y += bf_hi(wB0);
                aB1x += bf_lo(wB1); aB1y += bf_hi(wB1);
                aA0x += bf_lo(wA2); aA0y += bf_hi(wA2);
                aA1x += bf_lo(wA3); aA1y += bf_hi(wA3);
                aB0x += bf_lo(wB2); aB0y += bf_hi(wB2);
                aB1x += bf_lo(wB3); aB1y += bf_hi(wB3);
            }
            __syncwarp();
            bA += 32; bB += 32;
        }
        while (bA + 32 <= reA) {
            sidx[w][0][lane] = g_col[bA + lane];
            __syncwarp();
            #pragma unroll
            for (int q = 0; q < 8; q++) {
                int4 ja = iA4[q];
                unsigned int w0 = xh[ja.x * 32 + lane];
                unsigned int w1 = xh[ja.y * 32 + lane];
                unsigned int w2 = xh[ja.z * 32 + lane];
                unsigned int w3 = xh[ja.w * 32 + lane];
                aA0x += bf_lo(w0); aA0y += bf_hi(w0);
                aA1x += bf_lo(w1); aA1y += bf_hi(w1);
                aA0x += bf_lo(w2); aA0y += bf_hi(w2);
                aA1x += bf_lo(w3); aA1y += bf_hi(w3);
            }
            __syncwarp();
            bA += 32;
        }
        while (bB + 32 <= reB) {
            sidx[w][1][lane] = g_col[bB + lane];
            __syncwarp();
            #pragma unroll
            for (int q = 0; q < 8; q++) {
                int4 jb = iB4[q];
                unsigned int w0 = xh[jb.x * 32 + lane];
                unsigned int w1 = xh[jb.y * 32 + lane];
                unsigned int w2 = xh[jb.z * 32 + lane];
                unsigned int w3 = xh[jb.w * 32 + lane];
                aB0x += bf_lo(w0); aB0y += bf_hi(w0);
                aB1x += bf_lo(w1); aB1y += bf_hi(w1);
                aB0x += bf_lo(w2); aB0y += bf_hi(w2);
                aB1x += bf_lo(w3); aB1y += bf_hi(w3);
            }
            __syncwarp();
            bB += 32;
        }
        {
            int remA = reA - bA, remB = reB - bB;
            if (lane < remA) sidx[w][0][lane] = g_col[bA + lane];
            if (lane < remB) sidx[w][1][lane] = g_col[bB + lane];
            __syncwarp();
            int rem = remA > remB ? remA : remB;
            for (int t = 0; t < rem; t++) {
                if (t < remA) {
                    unsigned int wv = xh[sidx[w][0][t] * 32 + lane];
                    aA0x += bf_lo(wv); aA0y += bf_hi(wv);
                }
                if (t < remB) {
                    unsigned int wv = xh[sidx[w][1][t] * 32 + lane];
                    aB0x += bf_lo(wv); aB0y += bf_hi(wv);
                }
            }
            __syncwarp();
        }
        ((float2*)sm4[w][0])[lane] = make_float2(aA0x + aA1x, aA0y + aA1y);
        ((float2*)sm4[w][1])[lane] = make_float2(aB0x + aB1x, aB0y + aB1y);
        __syncwarp();

        float2 hA = sb1[lane], hB = sb1[lane];
        const float4* mAv = (const float4*)sm4[w][0];
        const float4* mBv = (const float4*)sm4[w][1];
        #pragma unroll
        for (int kk = 0; kk < 16; kk++) {
            float4 m4A = mAv[kk];
            float4 m4B = mBv[kk];
            float4 w0 = sW1q[2 * kk][lane];
            float4 w1 = sW1q[2 * kk + 1][lane];
            hA.x = fmaf(m4A.x, w0.x, hA.x); hA.y = fmaf(m4A.x, w0.y, hA.y);
            hA.x = fmaf(m4A.y, w0.z, hA.x); hA.y = fmaf(m4A.y, w0.w, hA.y);
            hA.x = fmaf(m4A.z, w1.x, hA.x); hA.y = fmaf(m4A.z, w1.y, hA.y);
            hA.x = fmaf(m4A.w, w1.z, hA.x); hA.y = fmaf(m4A.w, w1.w, hA.y);
            hB.x = fmaf(m4B.x, w0.x, hB.x); hB.y = fmaf(m4B.x, w0.y, hB.y);
            hB.x = fmaf(m4B.y, w0.z, hB.x); hB.y = fmaf(m4B.y, w0.w, hB.y);
            hB.x = fmaf(m4B.z, w1.x, hB.x); hB.y = fmaf(m4B.z, w1.y, hB.y);
            hB.x = fmaf(m4B.w, w1.z, hB.x); hB.y = fmaf(m4B.w, w1.w, hB.y);
        }
        hA.x = lrelu(hA.x); hA.y = lrelu(hA.y);
        hB.x = lrelu(hB.x); hB.y = lrelu(hB.y);
        ((float2*)sh4[w][0])[lane] = hA;
        ((float2*)sh4[w][1])[lane] = hB;
        __syncwarp();

        float2 oA = sb2[lane], oB = sb2[lane];
        const float4* hAv = (const float4*)sh4[w][0];
        const float4* hBv = (const float4*)sh4[w][1];
        #pragma unroll
        for (int kk = 0; kk < 16; kk++) {
            float4 m4A = hAv[kk];
            float4 m4B = hBv[kk];
            float4 w0 = sW2q[2 * kk][lane];
            float4 w1 = sW2q[2 * kk + 1][lane];
            oA.x = fmaf(m4A.x, w0.x, oA.x); oA.y = fmaf(m4A.x, w0.y, oA.y);
            oA.x = fmaf(m4A.y, w0.z, oA.x); oA.y = fmaf(m4A.y, w0.w, oA.y);
            oA.x = fmaf(m4A.z, w1.x, oA.x); oA.y = fmaf(m4A.z, w1.y, oA.y);
            oA.x = fmaf(m4A.w, w1.z, oA.x); oA.y = fmaf(m4A.w, w1.w, oA.y);
            oB.x = fmaf(m4B.x, w0.x, oB.x); oB.y = fmaf(m4B.x, w0.y, oB.y);
            oB.x = fmaf(m4B.y, w0.z, oB.x); oB.y = fmaf(m4B.y, w0.w, oB.y);
            oB.x = fmaf(m4B.z, w1.x, oB.x); oB.y = fmaf(m4B.z, w1.y, oB.y);
            oB.x = fmaf(m4B.w, w1.z, oB.x); oB.y = fmaf(m4B.w, w1.w, oB.y);
        }
        o2[nA * 32 + lane] = oA;
        ssx += oA.x; ssy += oA.y; sqx += oA.x * oA.x; sqy += oA.y * oA.y;
        if (hasB) {
            o2[nB * 32 + lane] = oB;
            ssx += oB.x; ssy += oB.y; sqx += oB.x * oB.x; sqy += oB.y * oB.y;
        }
        __syncwarp();
    }

    atomicAdd(&bstat[2 * lane], ssx);
    atomicAdd(&bstat[2 * lane + 1], ssy);
    atomicAdd(&bstat[64 + 2 * lane], sqx);
    atomicAdd(&bstat[64 + 2 * lane + 1], sqy);
    __syncthreads();
    if (tid < 128) atomicAdd(&g_statsA[l][tid], bstat[tid]);
}

// ---------------- BN + leaky for z1/z2 ----------------------------------------
__global__ void k_bnapply(const float* __restrict__ g, const float* __restrict__ b,
                          int lz, int n) {
    __shared__ float ssc[64];
    __shared__ float ssh[64];
    int tid = threadIdx.x;
    int slot = lz - 1;
    if (tid < 64) {
        float inv = 1.0f / (float)n;
        float mean = g_statsA[slot][tid] * inv;
        float var = g_statsA[slot][64 + tid] * inv - mean * mean;
        float sc = g[tid] * rsqrtf(var + 1e-5f);
        ssc[tid] = sc;
        ssh[tid] = b[tid] - sc * mean;
    }
    __syncthreads();
    int i = blockIdx.x * blockDim.x + tid;
    if (i >= n * 32) return;
    int c = (i & 31) * 2;
    float2* z2 = (float2*)g_z[lz];
    float2 v = z2[i];
    v.x = lrelu(ssc[c] * v.x + ssh[c]);
    v.y = lrelu(ssc[c + 1] * v.y + ssh[c + 1]);
    z2[i] = v;
    g_zh[lz][i] = pack_bf16x2(v);
}

// ---------------- merged FC layer 1 (frozen R15 form) --------------------------
__global__ void __launch_bounds__(256) k_fcall(
    const float* __restrict__ fcW1, const float* __restrict__ fcb1,
    const float* __restrict__ bng, const float* __restrict__ bnb, int n)
{
    extern __shared__ float4 dyn[];
    float4* sWq = dyn;
    float4* sx4 = dyn + 4096;
    __shared__ float2 sb[32];
    __shared__ float  bstat[128];
    __shared__ float  ssc[64];
    __shared__ float  ssh[64];
    int tid = threadIdx.x;
    {
        const float2* wv = (const float2*)fcW1;
        for (int i = tid; i < 4096; i += 256) {
            int k2 = i >> 5, c = i & 31;
            float2 a = wv[(2 * k2) * 32 + c];
            float2 b = wv[(2 * k2 + 1) * 32 + c];
            sWq[k2 * 32 + c] = make_float4(a.x, a.y, b.x, b.y);
        }
        if (tid < 32) sb[tid] = ((const float2*)fcb1)[tid];
        if (tid < 128) bstat[tid] = 0.f;
        if (tid < 64) {
            float inv = 1.0f / (float)n;
            float mean = g_statsA[2][tid] * inv;
            float var = g_statsA[2][64 + tid] * inv - mean * mean;
            float sc = bng[tid] * rsqrtf(var + 1e-5f);
            ssc[tid] = sc;
            ssh[tid] = bnb[tid] - sc * mean;
        }
    }
    __syncthreads();

    const float2* z0 = (const float2*)g_z[0];
    const float2* z1 = (const float2*)g_z[1];
    const float2* zz2 = (const float2*)g_z[2];
    const float2* z3 = (const float2*)g_z[3];
    float2* u2 = (float2*)g_u;
    int w = tid >> 5, lane = tid & 31;
    float ssx = 0.f, ssy = 0.f, sqx = 0.f, sqy = 0.f;
    int gw = (blockIdx.x * 256 + tid) >> 5;
    int nw = (gridDim.x * 256) >> 5;
    float scx = ssc[2 * lane], scy = ssc[2 * lane + 1];
    float shx = ssh[2 * lane], shy = ssh[2 * lane + 1];

    float2* sxA = (float2*)(sx4 + (w * 2 + 0) * 64);
    float2* sxB = (float2*)(sx4 + (w * 2 + 1) * 64);

    for (int base = gw * 2; base < n; base += nw * 2) {
        int nA = base, nB = base + 1;
        bool hasB = (nB < n);
        {
            float2 v3 = z3[nA * 32 + lane];
            v3.x = lrelu(scx * v3.x + shx);
            v3.y = lrelu(scy * v3.y + shy);
            sxA[lane]      = z0[nA * 32 + lane];
            sxA[32 + lane] = z1[nA * 32 + lane];
            sxA[64 + lane] = zz2[nA * 32 + lane];
            sxA[96 + lane] = v3;
        }
        if (hasB) {
            float2 v3 = z3[nB * 32 + lane];
            v3.x = lrelu(scx * v3.x + shx);
            v3.y = lrelu(scy * v3.y + shy);
            sxB[lane]      = z0[nB * 32 + lane];
            sxB[32 + lane] = z1[nB * 32 + lane];
            sxB[64 + lane] = zz2[nB * 32 + lane];
            sxB[96 + lane] = v3;
        }
        __syncwarp();

        float2 uA = sb[lane], uB = sb[lane];
        const float4* xAv = (const float4*)sxA;
        const float4* xBv = (const float4*)sxB;
        #pragma unroll
        for (int kk = 0; kk < 64; kk++) {
            float4 m4A = xAv[kk];
            float4 m4B = xBv[kk];
            float4 w0 = sWq[(2 * kk) * 32 + lane];
            float4 w1 = sWq[(2 * kk + 1) * 32 + lane];
            uA.x = fmaf(m4A.x, w0.x, uA.x); uA.y = fmaf(m4A.x, w0.y, uA.y);
            uA.x = fmaf(m4A.y, w0.z, uA.x); uA.y = fmaf(m4A.y, w0.w, uA.y);
            uA.x = fmaf(m4A.z, w1.x, uA.x); uA.y = fmaf(m4A.z, w1.y, uA.y);
            uA.x = fmaf(m4A.w, w1.z, uA.x); uA.y = fmaf(m4A.w, w1.w, uA.y);
            uB.x = fmaf(m4B.x, w0.x, uB.x); uB.y = fmaf(m4B.x, w0.y, uB.y);
            uB.x = fmaf(m4B.y, w0.z, uB.x); uB.y = fmaf(m4B.y, w0.w, uB.y);
            uB.x = fmaf(m4B.z, w1.x, uB.x); uB.y = fmaf(m4B.z, w1.y, uB.y);
            uB.x = fmaf(m4B.w, w1.z, uB.x); uB.y = fmaf(m4B.w, w1.w, uB.y);
        }
        u2[nA * 32 + lane] = uA;
        ssx += uA.x; ssy += uA.y; sqx += uA.x * uA.x; sqy += uA.y * uA.y;
        if (hasB) {
            u2[nB * 32 + lane] = uB;
            ssx += uB.x; ssy += uB.y; sqx += uB.x * uB.x; sqy += uB.y * uB.y;
        }
        __syncwarp();
    }

    atomicAdd(&bstat[2 * lane], ssx);
    atomicAdd(&bstat[2 * lane + 1], ssy);
    atomicAdd(&bstat[64 + 2 * lane], sqx);
    atomicAdd(&bstat[64 + 2 * lane + 1], sqy);
    __syncthreads();
    if (tid < 128) atomicAdd(&g_statsA[3][tid], bstat[tid]);
}

// ---------------- head --------------------------------------------------------
__global__ void k_head(const float* __restrict__ g, const float* __restrict__ b,
                       const float* __restrict__ fcW2, const float* __restrict__ fcb2,
                       float* __restrict__ out, int n) {
    __shared__ float ssc[64];
    __shared__ float ssh[64];
    int tid = threadIdx.x;
    if (tid < 64) {
        float inv = 1.0f / (float)n;
        float mean = g_statsA[3][tid] * inv;
        float var = g_statsA[3][64 + tid] * inv - mean * mean;
        float sc = g[tid] * rsqrtf(var + 1e-5f);
        ssc[tid] = sc;
        ssh[tid] = b[tid] - sc * mean;
    }
    __syncthreads();
    int gt = blockIdx.x * blockDim.x + tid;
    int node = gt >> 5, lane = gt & 31;
    if (node >= n) return;
    float2 u = ((const float2*)g_u)[node * 32 + lane];
    int c = 2 * lane;
    float y0 = lrelu(ssc[c] * u.x + ssh[c]);
    float y1 = lrelu(ssc[c + 1] * u.y + ssh[c + 1]);
    float p = y0 * fcW2[c] + y1 * fcW2[c + 1];
    #pragma unroll
    for (int o = 16; o > 0; o >>= 1) p += __shfl_xor_sync(0xffffffffu, p, o);
    if (lane == 0) out[node] = 1.0f / (1.0f + expf(-(p + fcb2[0])));
}

// ---------------- launch -------------------------------------------------------
extern "C" void kernel_launch(void* const* d_in, const int* in_sizes, int n_in,
                              void* d_out, int out_size) {
    const int*   node_deg = (const int*)d_in[0];
    const int*   edge_idx = (const int*)d_in[1];
    const float* embed    = (const float*)d_in[2];
    const float* eps      = (const float*)d_in[3];
    const float* W1       = (const float*)d_in[4];
    const float* b1       = (const float*)d_in[5];
    const float* W2       = (const float*)d_in[6];
    const float* b2       = (const float*)d_in[7];
    const float* bn_g     = (const float*)d_in[8];
    const float* bn_b     = (const float*)d_in[9];
    const float* fcW1     = (const float*)d_in[10];
    const float* fcb1     = (const float*)d_in[11];
    const float* fc_bn_g  = (const float*)d_in[12];
    const float* fc_bn_b  = (const float*)d_in[13];
    const float* fcW2     = (const float*)d_in[14];
    const float* fcb2     = (const float*)d_in[15];

    int n = in_sizes[0];
    int e = in_sizes[1] / 2;
    const int* src = edge_idx;
    const int* dst = edge_idx + e;

    int elemBlocks = (n * 32 + 255) / 256;
    int nb = (n + 1023) / 1024;
    const int PGRID = 592;
    const int FCSMEM = 81920;
    const int FCGRID = 296;

    static bool attrSet = false;
    if (!attrSet) {
        cudaFuncSetAttribute(k_fcall, cudaFuncAttributeMaxDynamicSharedMemorySize, FCSMEM);
        attrSet = true;
    }

    bool vec4 = ((e & 3) == 0)
             && ((((unsigned long long)(size_t)src) & 15ull) == 0)
             && ((((unsigned long long)(size_t)dst) & 15ull) == 0);

    k_zero<<<(n + 255) / 256, 256>>>(n);
    if (vec4) {
        k_hist4e<<<1024, 256>>>(dst, e / 4, e, node_deg, embed, n);
    } else {
        k_hist<<<1024, 256>>>(dst, e);
        k_embed<<<elemBlocks, 256>>>(node_deg, embed, n);
    }
    k_scan1<<<nb, 1024>>>(n);
    k_scan2<<<1, 128>>>(nb);
    k_scan3<<<nb, 1024>>>(n, e);
    if (vec4) k_fill4<<<1024, 256>>>(src, dst, e / 4, e);
    else      k_fill<<<1024, 256>>>(src, dst, e);

    for (int l = 0; l < 2; l++) {
        k_layer<<<PGRID, 256>>>(W1, b1, W2, b2, eps, l, n);
        k_bnapply<<<elemBlocks, 256>>>(bn_g + l * 64, bn_b + l * 64, l + 1, n);
    }
    k_layer<<<PGRID, 256>>>(W1, b1, W2, b2, eps, 2, n);

    k_fcall<<<FCGRID, 256, FCSMEM>>>(fcW1, fcb1, bn_g + 128, bn_b + 128, n);
    k_head<<<elemBlocks, 256>>>(fc_bn_g, fc_bn_b, fcW2, fcb2, (float*)d_out, n);
}